// round 3
// baseline (speedup 1.0000x reference)
#include <cuda_runtime.h>
#include <math.h>

#define NR 768
#define NH 12

// ---------------- scratch ----------------
__device__ float g_proj[NR * 1152];            // q[0:192) kv[192:576) qp[576:720) kvp[720:1152)
__device__ float g_qpts[NR * NH * 12];         // [(n*12+h)*12 + p*3+d]
__device__ float g_kpT [NH * NR * 12];         // [(h*768+k)*12 + p*3+d]
__device__ float g_vpT [NH * NR * 24];         // [(h*768+k)*24 + vp*3+d]
__device__ float g_kT  [NH * NR * 16];         // [(h*768+k)*16 + c]
__device__ float g_vT  [NH * NR * 16];
__device__ float g_bb  [(size_t)NH * NR * NR]; // [h][q][k]
__device__ float g_attn[(size_t)NH * NR * NR]; // [h][q][k]
__device__ float g_cat [NR * 2112];

// ---------------- generic GEMM: 64x32 tile, 256 thr, 4x2 micro, BK=16 ----------------
__global__ __launch_bounds__(256) void gemm_k(
    const float* __restrict__ A, const float* __restrict__ B,
    const float* __restrict__ bias, float* __restrict__ Cext,
    int M, int Ncol, int K, int ldc, int srcSel, int dstSel, int colOff) {
    __shared__ float As[16][68];
    __shared__ float Bs[16][32];
    const float* Ap = srcSel ? g_cat : A;
    const int tid = threadIdx.x;
    const int row0 = blockIdx.y * 64, col0 = blockIdx.x * 32;
    const int tx = tid & 15, ty = tid >> 4;
    const int ar = tid >> 2, ak = (tid & 3) * 4;
    const int bk = tid >> 4, bc = (tid & 15) * 2;
    float acc[4][2] = {};
    for (int k0 = 0; k0 < K; k0 += 16) {
        float4 av = *(const float4*)(Ap + (size_t)(row0 + ar) * K + k0 + ak);
        As[ak + 0][ar] = av.x; As[ak + 1][ar] = av.y;
        As[ak + 2][ar] = av.z; As[ak + 3][ar] = av.w;
        int gc = col0 + bc;
        float2 bv = make_float2(0.f, 0.f);
        if (gc < Ncol) bv = *(const float2*)(B + (size_t)(k0 + bk) * Ncol + gc);
        Bs[bk][bc] = bv.x; Bs[bk][bc + 1] = bv.y;
        __syncthreads();
        #pragma unroll
        for (int kk = 0; kk < 16; kk++) {
            float4 a4 = *(const float4*)&As[kk][ty * 4];
            float2 b2 = *(const float2*)&Bs[kk][tx * 2];
            acc[0][0] += a4.x * b2.x; acc[0][1] += a4.x * b2.y;
            acc[1][0] += a4.y * b2.x; acc[1][1] += a4.y * b2.y;
            acc[2][0] += a4.z * b2.x; acc[2][1] += a4.z * b2.y;
            acc[3][0] += a4.w * b2.x; acc[3][1] += a4.w * b2.y;
        }
        __syncthreads();
    }
    float* C = dstSel ? Cext : (g_proj + colOff);
    int ld = dstSel ? ldc : 1152;
    #pragma unroll
    for (int i = 0; i < 4; i++) {
        int r = row0 + ty * 4 + i;
        #pragma unroll
        for (int j = 0; j < 2; j++) {
            int c = col0 + tx * 2 + j;
            if (c < Ncol) C[(size_t)r * ld + c] = acc[i][j] + bias[c];
        }
    }
}

// ---------------- points: rotate/translate, transpose k/v ----------------
__global__ __launch_bounds__(192) void k1b_points(const float* __restrict__ rot,
                                                  const float* __restrict__ trans) {
    const int n = blockIdx.x, tid = threadIdx.x;
    __shared__ float R[9], T[3];
    if (tid < 9) R[tid] = rot[n * 9 + tid];
    else if (tid >= 16 && tid < 19) T[tid - 16] = trans[n * 3 + tid - 16];
    __syncthreads();
    if (tid < 48) {
        int h = tid >> 2, p = tid & 3;
        const float* b = &g_proj[(size_t)n * 1152 + 576];
        float p0 = b[h * 4 + p], p1 = b[48 + h * 4 + p], p2 = b[96 + h * 4 + p];
        float* o = &g_qpts[((size_t)n * NH + h) * 12 + p * 3];
        o[0] = R[0]*p0 + R[1]*p1 + R[2]*p2 + T[0];
        o[1] = R[3]*p0 + R[4]*p1 + R[5]*p2 + T[1];
        o[2] = R[6]*p0 + R[7]*p1 + R[8]*p2 + T[2];
    } else {
        int idx = tid - 48, h = idx / 12, p = idx % 12;
        const float* b = &g_proj[(size_t)n * 1152 + 720];
        float p0 = b[h * 12 + p], p1 = b[144 + h * 12 + p], p2 = b[288 + h * 12 + p];
        float x = R[0]*p0 + R[1]*p1 + R[2]*p2 + T[0];
        float y = R[3]*p0 + R[4]*p1 + R[5]*p2 + T[1];
        float zc = R[6]*p0 + R[7]*p1 + R[8]*p2 + T[2];
        float* o = (p < 4) ? &g_kpT[((size_t)h * NR + n) * 12 + p * 3]
                           : &g_vpT[((size_t)h * NR + n) * 24 + (p - 4) * 3];
        o[0] = x; o[1] = y; o[2] = zc;
    }
    for (int t = tid; t < 384; t += 192) {
        int h = t >> 5, cc = t & 31;
        float val = g_proj[(size_t)n * 1152 + 192 + h * 32 + cc];
        if (cc < 16) g_kT[((size_t)h * NR + n) * 16 + cc] = val;
        else         g_vT[((size_t)h * NR + n) * 16 + cc - 16] = val;
    }
}

// ---------------- b_bias: z[q,k,:] @ Wb + bb -> g_bb[h][q][k] ----------------
__global__ __launch_bounds__(128) void k2_bbias(const float* __restrict__ z,
                                                const float* __restrict__ Wb,
                                                const float* __restrict__ bbv) {
    __shared__ float zS[256][33];
    __shared__ float WbS[128 * 12];
    const int tid = threadIdx.x;
    const int q = blockIdx.x / 3, k0 = (blockIdx.x % 3) * 256;
    for (int t = tid; t < 1536; t += 128) WbS[t] = Wb[t];
    float acc0[12] = {}, acc1[12] = {};
    const float* zbase = z + ((size_t)q * NR + k0) * 128;
    for (int cc = 0; cc < 128; cc += 32) {
        __syncthreads();
        #pragma unroll
        for (int it = 0; it < 16; it++) {
            int lin = it * 128 + tid;
            int r = lin >> 3, j = lin & 7;
            float4 v = *(const float4*)(zbase + (size_t)r * 128 + cc + j * 4);
            zS[r][j*4+0] = v.x; zS[r][j*4+1] = v.y; zS[r][j*4+2] = v.z; zS[r][j*4+3] = v.w;
        }
        __syncthreads();
        #pragma unroll 4
        for (int c = 0; c < 32; c++) {
            float z0 = zS[tid][c], z1 = zS[tid + 128][c];
            const float4* wp = (const float4*)(WbS + (cc + c) * 12);
            float4 w0 = wp[0], w1 = wp[1], w2 = wp[2];
            float wv[12] = {w0.x,w0.y,w0.z,w0.w, w1.x,w1.y,w1.z,w1.w, w2.x,w2.y,w2.z,w2.w};
            #pragma unroll
            for (int h = 0; h < 12; h++) {
                acc0[h] = fmaf(z0, wv[h], acc0[h]);
                acc1[h] = fmaf(z1, wv[h], acc1[h]);
            }
        }
    }
    #pragma unroll
    for (int h = 0; h < 12; h++) {
        size_t base = ((size_t)h * NR + q) * NR + k0;
        g_bb[base + tid]       = acc0[h] + bbv[h];
        g_bb[base + 128 + tid] = acc1[h] + bbv[h];
    }
}

// ---------------- logits + softmax ----------------
__global__ __launch_bounds__(256) void k3_attn(const float* __restrict__ hw_in,
                                               const float* __restrict__ mask) {
    const int q = blockIdx.x, h = blockIdx.y, tid = threadIdx.x;
    __shared__ float qS[16], qpS[12], red[8];
    if (tid < 16) qS[tid] = g_proj[(size_t)q * 1152 + h * 16 + tid];
    if (tid >= 32 && tid < 44) qpS[tid - 32] = g_qpts[((size_t)q * NH + h) * 12 + tid - 32];
    __syncthreads();
    float qv[16], qr[12];
    #pragma unroll
    for (int c = 0; c < 16; c++) qv[c] = qS[c];
    float qn = 0.f;
    #pragma unroll
    for (int j = 0; j < 12; j++) { qr[j] = qpS[j]; qn += qr[j] * qr[j]; }
    float mq = mask[q];
    float x = hw_in[h];
    float hw = -0.5f * log1pf(__expf(x)) * 0.13608276348795434f;  // -0.5*softplus*sqrt(1/54)
    float l[3];
    #pragma unroll
    for (int i = 0; i < 3; i++) {
        int k = i * 256 + tid;
        const float4* kp4 = (const float4*)(g_kT + ((size_t)h * NR + k) * 16);
        float4 a0 = kp4[0], a1 = kp4[1], a2 = kp4[2], a3 = kp4[3];
        float qk = qv[0]*a0.x + qv[1]*a0.y + qv[2]*a0.z + qv[3]*a0.w
                 + qv[4]*a1.x + qv[5]*a1.y + qv[6]*a1.z + qv[7]*a1.w
                 + qv[8]*a2.x + qv[9]*a2.y + qv[10]*a2.z + qv[11]*a2.w
                 + qv[12]*a3.x + qv[13]*a3.y + qv[14]*a3.z + qv[15]*a3.w;
        const float4* pp4 = (const float4*)(g_kpT + ((size_t)h * NR + k) * 12);
        float4 p0 = pp4[0], p1 = pp4[1], p2 = pp4[2];
        float kpv[12] = {p0.x,p0.y,p0.z,p0.w, p1.x,p1.y,p1.z,p1.w, p2.x,p2.y,p2.z,p2.w};
        float dot = 0.f, kn = 0.f;
        #pragma unroll
        for (int j = 0; j < 12; j++) { dot += qr[j] * kpv[j]; kn += kpv[j] * kpv[j]; }
        float bb = g_bb[((size_t)h * NR + q) * NR + k];
        float mk = mask[k];
        l[i] = 0.14433756729740643f * qk + 0.5773502691896258f * bb
             + hw * (qn + kn - 2.f * dot) + 100000.f * (mq * mk - 1.f);
    }
    const int lane = tid & 31, wid = tid >> 5;
    float m = fmaxf(fmaxf(l[0], l[1]), l[2]);
    #pragma unroll
    for (int off = 16; off; off >>= 1) m = fmaxf(m, __shfl_xor_sync(~0u, m, off));
    if (lane == 0) red[wid] = m;
    __syncthreads();
    float bm = red[0];
    #pragma unroll
    for (int w = 1; w < 8; w++) bm = fmaxf(bm, red[w]);
    __syncthreads();
    float e0 = __expf(l[0] - bm), e1 = __expf(l[1] - bm), e2 = __expf(l[2] - bm);
    float sm = e0 + e1 + e2;
    #pragma unroll
    for (int off = 16; off; off >>= 1) sm += __shfl_xor_sync(~0u, sm, off);
    if (lane == 0) red[wid] = sm;
    __syncthreads();
    float bs = 0.f;
    #pragma unroll
    for (int w = 0; w < 8; w++) bs += red[w];
    float inv = 1.0f / bs;
    size_t ob = ((size_t)h * NR + q) * NR + tid;
    g_attn[ob]       = e0 * inv;
    g_attn[ob + 256] = e1 * inv;
    g_attn[ob + 512] = e2 * inv;
}

// ---------------- o + o_pt + norms -> g_cat ----------------
__global__ __launch_bounds__(160) void k4_out(const float* __restrict__ rot,
                                              const float* __restrict__ trans) {
    const int h = blockIdx.x, q = blockIdx.y, tid = threadIdx.x;
    const int part = tid / 40, col = tid % 40;
    __shared__ float sums[4][40];
    __shared__ float fin[40];
    const float* arow = &g_attn[((size_t)h * NR + q) * NR];
    float acc = 0.f;
    int k0 = part * 192;
    if (col < 16) {
        const float* vb = g_vT + (size_t)h * NR * 16 + col;
        for (int k = k0; k < k0 + 192; k++) acc = fmaf(arow[k], vb[(size_t)k * 16], acc);
    } else {
        const float* vb = g_vpT + (size_t)h * NR * 24 + (col - 16);
        for (int k = k0; k < k0 + 192; k++) acc = fmaf(arow[k], vb[(size_t)k * 24], acc);
    }
    sums[part][col] = acc;
    __syncthreads();
    if (tid < 40) fin[tid] = sums[0][tid] + sums[1][tid] + sums[2][tid] + sums[3][tid];
    __syncthreads();
    if (tid < 16) {
        g_cat[(size_t)q * 2112 + h * 16 + tid] = fin[tid];
    } else if (tid >= 32 && tid < 40) {
        int p = tid - 32;
        const float* R = rot + q * 9;
        const float* T = trans + q * 3;
        float dx = fin[16 + p*3 + 0] - T[0];
        float dy = fin[16 + p*3 + 1] - T[1];
        float dz = fin[16 + p*3 + 2] - T[2];
        float lx = R[0]*dx + R[3]*dy + R[6]*dz;
        float ly = R[1]*dx + R[4]*dy + R[7]*dz;
        float lz = R[2]*dx + R[5]*dy + R[8]*dz;
        float nrm = sqrtf(lx*lx + ly*ly + lz*lz + 1e-8f);
        size_t b = (size_t)q * 2112 + h * 8 + p;
        g_cat[b + 192] = lx; g_cat[b + 288] = ly;
        g_cat[b + 384] = lz; g_cat[b + 480] = nrm;
    }
}

// ---------------- o_pair: attn @ z -> g_cat[:,576:2112] ----------------
__global__ __launch_bounds__(256) void k5_opair(const float* __restrict__ z) {
    const int q = blockIdx.x, tid = threadIdx.x;
    const int part = tid >> 6, cq = tid & 63;
    __shared__ float aS[384 * 12];           // [k][h]
    __shared__ float redS[3][12][64][2];
    float2 acc[12];
    #pragma unroll
    for (int h = 0; h < 12; h++) acc[h] = make_float2(0.f, 0.f);
    for (int half = 0; half < 2; half++) {
        int kb = half * 384;
        __syncthreads();
        for (int lin = tid; lin < 384 * 12; lin += 256) {
            int hh = lin / 384, kk = lin % 384;
            aS[kk * 12 + hh] = g_attn[((size_t)hh * NR + q) * NR + kb + kk];
        }
        __syncthreads();
        int klo = part * 96;
        for (int kk = klo; kk < klo + 96; kk++) {
            float2 zv = *(const float2*)(z + ((size_t)q * NR + kb + kk) * 128 + 2 * cq);
            const float4* ap = (const float4*)(aS + kk * 12);
            float4 A0 = ap[0], A1 = ap[1], A2 = ap[2];
            float av[12] = {A0.x,A0.y,A0.z,A0.w, A1.x,A1.y,A1.z,A1.w, A2.x,A2.y,A2.z,A2.w};
            #pragma unroll
            for (int h = 0; h < 12; h++) {
                acc[h].x = fmaf(av[h], zv.x, acc[h].x);
                acc[h].y = fmaf(av[h], zv.y, acc[h].y);
            }
        }
    }
    if (part > 0) {
        #pragma unroll
        for (int h = 0; h < 12; h++) {
            redS[part - 1][h][cq][0] = acc[h].x;
            redS[part - 1][h][cq][1] = acc[h].y;
        }
    }
    __syncthreads();
    if (part == 0) {
        #pragma unroll
        for (int h = 0; h < 12; h++) {
            float2 r = acc[h];
            r.x += redS[0][h][cq][0] + redS[1][h][cq][0] + redS[2][h][cq][0];
            r.y += redS[0][h][cq][1] + redS[1][h][cq][1] + redS[2][h][cq][1];
            *(float2*)(g_cat + (size_t)q * 2112 + 576 + h * 128 + 2 * cq) = r;
        }
    }
}

extern "C" void kernel_launch(void* const* d_in, const int* in_sizes, int n_in,
                              void* d_out, int out_size) {
    const float* s     = (const float*)d_in[0];
    const float* z     = (const float*)d_in[1];
    const float* rot   = (const float*)d_in[2];
    const float* trans = (const float*)d_in[3];
    const float* mask  = (const float*)d_in[4];
    const float* Wq    = (const float*)d_in[5];
    const float* bq    = (const float*)d_in[6];
    const float* Wqp   = (const float*)d_in[7];
    const float* bqp   = (const float*)d_in[8];
    const float* Wkv   = (const float*)d_in[9];
    const float* bkv   = (const float*)d_in[10];
    const float* Wkvp  = (const float*)d_in[11];
    const float* bkvp  = (const float*)d_in[12];
    const float* Wb    = (const float*)d_in[13];
    const float* bbv   = (const float*)d_in[14];
    const float* hw    = (const float*)d_in[15];
    const float* Wout  = (const float*)d_in[16];
    const float* bout  = (const float*)d_in[17];
    float* out = (float*)d_out;

    gemm_k<<<dim3(6, 12), 256>>>(s, Wq,   bq,   nullptr, NR, 192, 384, 1152, 0, 0, 0);
    gemm_k<<<dim3(12, 12), 256>>>(s, Wkv,  bkv,  nullptr, NR, 384, 384, 1152, 0, 0, 192);
    gemm_k<<<dim3(5, 12), 256>>>(s, Wqp,  bqp,  nullptr, NR, 144, 384, 1152, 0, 0, 576);
    gemm_k<<<dim3(14, 12), 256>>>(s, Wkvp, bkvp, nullptr, NR, 432, 384, 1152, 0, 0, 720);
    k1b_points<<<NR, 192>>>(rot, trans);
    k2_bbias<<<NR * 3, 128>>>(z, Wb, bbv);
    k3_attn<<<dim3(NR, NH), 256>>>(hw, mask);
    k4_out<<<dim3(NH, NR), 160>>>(rot, trans);
    k5_opair<<<NR, 256>>>(z);
    gemm_k<<<dim3(12, 12), 256>>>(nullptr, Wout, bout, out, NR, 384, 2112, 384, 1, 1, 0);
}

// round 4
// speedup vs baseline: 1.2753x; 1.2753x over previous
#include <cuda_runtime.h>
#include <math.h>

#define NR 768

typedef unsigned long long u64;
__device__ __forceinline__ u64 pk2(float lo, float hi){ u64 r; asm("mov.b64 %0,{%1,%2};":"=l"(r):"f"(lo),"f"(hi)); return r; }
__device__ __forceinline__ u64 bc2(float v){ return pk2(v,v); }
__device__ __forceinline__ void fma2(u64& d, u64 a, u64 b){ asm("fma.rn.f32x2 %0,%1,%2,%0;":"+l"(d):"l"(a),"l"(b)); }
__device__ __forceinline__ float2 up2(u64 v){ float2 r; asm("mov.b64 {%0,%1},%2;":"=f"(r.x),"=f"(r.y):"l"(v)); return r; }

// ---------------- scratch ----------------
__device__ float g_proj[NR * 1152];            // q[0:192) kv[192:576) qp[576:720) kvp[720:1152)
__device__ float g_qpts[NR * 12 * 12];
__device__ float g_kpT [12 * NR * 12];
__device__ float g_vpT [12 * NR * 24];
__device__ float g_kT  [12 * NR * 16];
__device__ float g_vT  [12 * NR * 16];
__device__ float g_bb  [(size_t)12 * NR * NR];
__device__ float g_attn[(size_t)12 * NR * NR];
__device__ float g_cat [NR * 2112];
__device__ float g_fin [2 * NR * 384];

// ---------------- GEMM: 64x64 tile, 256 thr, 4x4 micro (packed row pairs) ----------------
// mode 0: C = A @ B + bias -> g_proj[:, colOff:]   (lda = K)
// mode 2: split-K over g_cat (K=2112, halves of 1056) -> g_fin[blockIdx.z]
__global__ __launch_bounds__(256) void gemm2(const float* __restrict__ Aext,
    const float* __restrict__ B, const float* __restrict__ bias,
    int Ncol, int K, int mode, int colOff) {
    __shared__ __align__(16) float As[16][68];
    __shared__ __align__(16) float Bs[16][64];
    const int tid = threadIdx.x;
    const int row0 = blockIdx.y * 64, col0 = blockIdx.x * 64;
    const float* Ap; int lda, kBase, kIters;
    if (mode == 2) { Ap = g_cat; lda = 2112; kBase = blockIdx.z * 1056; kIters = 66; }
    else           { Ap = Aext;  lda = K;    kBase = 0;                kIters = K / 16; }
    const int ar = tid >> 2, ak = (tid & 3) * 4;
    const int bk = tid >> 4, bc = (tid & 15) * 4;
    const int ty = tid >> 4, tx = tid & 15;
    u64 acc[2][4] = {};
    const int gc = col0 + bc;
    float4 av = *(const float4*)(Ap + (size_t)(row0 + ar) * lda + kBase + ak);
    float4 bv = make_float4(0.f, 0.f, 0.f, 0.f);
    if (gc < Ncol) bv = *(const float4*)(B + (size_t)(kBase + bk) * Ncol + gc);
    for (int it = 0; it < kIters; it++) {
        As[ak + 0][ar] = av.x; As[ak + 1][ar] = av.y;
        As[ak + 2][ar] = av.z; As[ak + 3][ar] = av.w;
        *(float4*)&Bs[bk][bc] = bv;
        __syncthreads();
        if (it + 1 < kIters) {
            int k0 = kBase + (it + 1) * 16;
            av = *(const float4*)(Ap + (size_t)(row0 + ar) * lda + k0 + ak);
            if (gc < Ncol) bv = *(const float4*)(B + (size_t)(k0 + bk) * Ncol + gc);
        }
        #pragma unroll
        for (int kk = 0; kk < 16; kk++) {
            u64 a01 = *(const u64*)&As[kk][ty * 4];
            u64 a23 = *(const u64*)&As[kk][ty * 4 + 2];
            float4 b4 = *(const float4*)&Bs[kk][tx * 4];
            u64 b0 = bc2(b4.x), b1 = bc2(b4.y), b2 = bc2(b4.z), b3 = bc2(b4.w);
            fma2(acc[0][0], a01, b0); fma2(acc[0][1], a01, b1);
            fma2(acc[0][2], a01, b2); fma2(acc[0][3], a01, b3);
            fma2(acc[1][0], a23, b0); fma2(acc[1][1], a23, b1);
            fma2(acc[1][2], a23, b2); fma2(acc[1][3], a23, b3);
        }
        __syncthreads();
    }
    #pragma unroll
    for (int i = 0; i < 2; i++) {
        int r = row0 + ty * 4 + i * 2;
        #pragma unroll
        for (int j = 0; j < 4; j++) {
            int c = col0 + tx * 4 + j;
            float2 v = up2(acc[i][j]);
            if (mode == 2) {
                float* dst = g_fin + (size_t)blockIdx.z * (NR * 384);
                dst[(size_t)r * 384 + c]       = v.x;
                dst[(size_t)(r + 1) * 384 + c] = v.y;
            } else if (c < Ncol) {
                float bb = bias[c];
                g_proj[(size_t)r * 1152 + colOff + c]       = v.x + bb;
                g_proj[(size_t)(r + 1) * 1152 + colOff + c] = v.y + bb;
            }
        }
    }
}

__global__ __launch_bounds__(256) void kcomb(const float* __restrict__ bias, float* __restrict__ out) {
    int i = blockIdx.x * 256 + threadIdx.x;
    out[i] = g_fin[i] + g_fin[NR * 384 + i] + bias[i % 384];
}

// ---------------- points: rotate/translate, transpose k/v ----------------
__global__ __launch_bounds__(192) void k1b_points(const float* __restrict__ rot,
                                                  const float* __restrict__ trans) {
    const int n = blockIdx.x, tid = threadIdx.x;
    __shared__ float R[9], T[3];
    if (tid < 9) R[tid] = rot[n * 9 + tid];
    else if (tid >= 16 && tid < 19) T[tid - 16] = trans[n * 3 + tid - 16];
    __syncthreads();
    if (tid < 48) {
        int h = tid >> 2, p = tid & 3;
        const float* b = &g_proj[(size_t)n * 1152 + 576];
        float p0 = b[h * 4 + p], p1 = b[48 + h * 4 + p], p2 = b[96 + h * 4 + p];
        float* o = &g_qpts[((size_t)n * 12 + h) * 12 + p * 3];
        o[0] = R[0]*p0 + R[1]*p1 + R[2]*p2 + T[0];
        o[1] = R[3]*p0 + R[4]*p1 + R[5]*p2 + T[1];
        o[2] = R[6]*p0 + R[7]*p1 + R[8]*p2 + T[2];
    } else {
        int idx = tid - 48, h = idx / 12, p = idx % 12;
        const float* b = &g_proj[(size_t)n * 1152 + 720];
        float p0 = b[h * 12 + p], p1 = b[144 + h * 12 + p], p2 = b[288 + h * 12 + p];
        float x = R[0]*p0 + R[1]*p1 + R[2]*p2 + T[0];
        float y = R[3]*p0 + R[4]*p1 + R[5]*p2 + T[1];
        float zc = R[6]*p0 + R[7]*p1 + R[8]*p2 + T[2];
        float* o = (p < 4) ? &g_kpT[((size_t)h * NR + n) * 12 + p * 3]
                           : &g_vpT[((size_t)h * NR + n) * 24 + (p - 4) * 3];
        o[0] = x; o[1] = y; o[2] = zc;
    }
    for (int t = tid; t < 384; t += 192) {
        int h = t >> 5, cc = t & 31;
        float val = g_proj[(size_t)n * 1152 + 192 + h * 32 + cc];
        if (cc < 16) g_kT[((size_t)h * NR + n) * 16 + cc] = val;
        else         g_vT[((size_t)h * NR + n) * 16 + cc - 16] = val;
    }
}

// ---------------- b_bias (FFMA2 over h-pairs) ----------------
__global__ __launch_bounds__(128) void k2_bbias(const float* __restrict__ z,
                                                const float* __restrict__ Wb,
                                                const float* __restrict__ bbv) {
    __shared__ float zS[256][33];
    __shared__ __align__(16) float WbS[1536];
    const int tid = threadIdx.x;
    const int q = blockIdx.x / 3, k0 = (blockIdx.x % 3) * 256;
    for (int t = tid; t < 1536; t += 128) WbS[t] = Wb[t];
    u64 acc0[6] = {}, acc1[6] = {};
    const float* zbase = z + ((size_t)q * NR + k0) * 128;
    for (int cc = 0; cc < 128; cc += 32) {
        __syncthreads();
        #pragma unroll
        for (int itl = 0; itl < 16; itl++) {
            int lin = itl * 128 + tid;
            int r = lin >> 3, j = lin & 7;
            float4 v = *(const float4*)(zbase + (size_t)r * 128 + cc + j * 4);
            zS[r][j*4+0] = v.x; zS[r][j*4+1] = v.y; zS[r][j*4+2] = v.z; zS[r][j*4+3] = v.w;
        }
        __syncthreads();
        #pragma unroll 4
        for (int c = 0; c < 32; c++) {
            u64 z0 = bc2(zS[tid][c]), z1 = bc2(zS[tid + 128][c]);
            const u64* wp = (const u64*)(WbS + (cc + c) * 12);
            #pragma unroll
            for (int hp = 0; hp < 6; hp++) { fma2(acc0[hp], wp[hp], z0); fma2(acc1[hp], wp[hp], z1); }
        }
    }
    #pragma unroll
    for (int hp = 0; hp < 6; hp++) {
        float2 a0 = up2(acc0[hp]), a1 = up2(acc1[hp]);
        size_t b0 = ((size_t)(2*hp) * NR + q) * NR + k0;
        size_t b1 = ((size_t)(2*hp+1) * NR + q) * NR + k0;
        g_bb[b0 + tid]       = a0.x + bbv[2*hp];
        g_bb[b0 + 128 + tid] = a1.x + bbv[2*hp];
        g_bb[b1 + tid]       = a0.y + bbv[2*hp+1];
        g_bb[b1 + 128 + tid] = a1.y + bbv[2*hp+1];
    }
}

// ---------------- logits + softmax, q-tile of 8, warp-per-q ----------------
__global__ __launch_bounds__(256) void k3_attn(const float* __restrict__ hw_in,
                                               const float* __restrict__ mask) {
    const int h = blockIdx.y, qt = blockIdx.x, tid = threadIdx.x;
    const int qi = tid >> 5, lane = tid & 31;
    const int q = qt * 8 + qi;
    __shared__ __align__(16) float kTs[256][18];
    __shared__ __align__(16) float kps[256][14];
    __shared__ float kns[256], kms[256];
    u64 qp2[8]; const u64* qsrc = (const u64*)(g_proj + (size_t)q * 1152 + h * 16);
    #pragma unroll
    for (int j = 0; j < 8; j++) qp2[j] = qsrc[j];
    u64 qr2[6]; const u64* qpsrc = (const u64*)(g_qpts + ((size_t)q * 12 + h) * 12);
    float qn = 0.f;
    #pragma unroll
    for (int j = 0; j < 6; j++) { qr2[j] = qpsrc[j]; float2 v = up2(qr2[j]); qn += v.x*v.x + v.y*v.y; }
    const float mq = mask[q];
    const float hw = -0.5f * log1pf(__expf(hw_in[h])) * 0.13608276348795434f;
    float lreg[24];
    for (int c3 = 0; c3 < 3; c3++) {
        int ck = c3 * 256;
        __syncthreads();
        #pragma unroll
        for (int l = 0; l < 8; l++) {
            int e = l * 256 + tid; int r = e >> 3, c2 = e & 7;
            *(float2*)&kTs[r][c2*2] = *(const float2*)(g_kT + ((size_t)h * NR + ck + r) * 16 + c2*2);
        }
        #pragma unroll
        for (int l = 0; l < 6; l++) {
            int e = l * 256 + tid; int r = e / 6, c2 = e % 6;
            *(float2*)&kps[r][c2*2] = *(const float2*)(g_kpT + ((size_t)h * NR + ck + r) * 12 + c2*2);
        }
        kms[tid] = mask[ck + tid];
        __syncthreads();
        float kn = 0.f;
        #pragma unroll
        for (int j = 0; j < 12; j++) kn += kps[tid][j] * kps[tid][j];
        kns[tid] = kn;
        __syncthreads();
        #pragma unroll
        for (int kk = 0; kk < 8; kk++) {
            int kl = kk * 32 + lane;
            const u64* kt2 = (const u64*)kTs[kl];
            u64 s = 0;
            #pragma unroll
            for (int j = 0; j < 8; j++) fma2(s, qp2[j], kt2[j]);
            const u64* kp2 = (const u64*)kps[kl];
            u64 sp = 0;
            #pragma unroll
            for (int j = 0; j < 6; j++) fma2(sp, qr2[j], kp2[j]);
            float2 sv = up2(s), spv = up2(sp);
            float qk = sv.x + sv.y, dt = spv.x + spv.y;
            float bbval = g_bb[((size_t)h * NR + q) * NR + ck + kl];
            lreg[c3*8+kk] = 0.14433756729740643f * qk + 0.5773502691896258f * bbval
                          + hw * (qn + kns[kl] - 2.f * dt) + 100000.f * (mq * kms[kl] - 1.f);
        }
    }
    float m = lreg[0];
    #pragma unroll
    for (int t = 1; t < 24; t++) m = fmaxf(m, lreg[t]);
    #pragma unroll
    for (int o = 16; o; o >>= 1) m = fmaxf(m, __shfl_xor_sync(~0u, m, o));
    float ssum = 0.f;
    #pragma unroll
    for (int t = 0; t < 24; t++) { lreg[t] = __expf(lreg[t] - m); ssum += lreg[t]; }
    #pragma unroll
    for (int o = 16; o; o >>= 1) ssum += __shfl_xor_sync(~0u, ssum, o);
    float inv = 1.f / ssum;
    size_t ob = ((size_t)h * NR + q) * NR;
    #pragma unroll
    for (int c3 = 0; c3 < 3; c3++)
        #pragma unroll
        for (int kk = 0; kk < 8; kk++)
            g_attn[ob + c3*256 + kk*32 + lane] = lreg[c3*8+kk] * inv;
}

// ---------------- o + o_pt as tiled GEMM (64 q x 40 cols) ----------------
__global__ __launch_bounds__(256) void k4_out(const float* __restrict__ rot,
                                              const float* __restrict__ trans) {
    const int h = blockIdx.x, q0 = blockIdx.y * 64, tid = threadIdx.x;
    const int ty = tid >> 3, tx = tid & 7;
    __shared__ __align__(16) float As[64][66];
    __shared__ float Vs[64][41];
    __shared__ float fin[64][41];
    u64 acc[5] = {};
    for (int kc = 0; kc < 12; kc++) {
        int k0 = kc * 64;
        __syncthreads();
        #pragma unroll
        for (int l = 0; l < 4; l++) {
            int e = l * 256 + tid; int r = e >> 4, c4 = e & 15;
            float4 v = *(const float4*)(g_attn + ((size_t)h * NR + q0 + r) * NR + k0 + c4*4);
            As[c4*4+0][r] = v.x; As[c4*4+1][r] = v.y;
            As[c4*4+2][r] = v.z; As[c4*4+3][r] = v.w;
        }
        #pragma unroll
        for (int l = 0; l < 10; l++) {
            int e = l * 256 + tid; int k = e / 40, c = e % 40;
            float vv = (c < 16) ? g_vT[((size_t)h * NR + k0 + k) * 16 + c]
                                : g_vpT[((size_t)h * NR + k0 + k) * 24 + c - 16];
            Vs[k][c] = vv;
        }
        __syncthreads();
        #pragma unroll 4
        for (int kk = 0; kk < 64; kk++) {
            u64 a = *(const u64*)&As[kk][ty * 2];
            #pragma unroll
            for (int j = 0; j < 5; j++) { u64 b = bc2(Vs[kk][tx*5+j]); fma2(acc[j], a, b); }
        }
    }
    __syncthreads();
    #pragma unroll
    for (int j = 0; j < 5; j++) {
        float2 v = up2(acc[j]);
        fin[ty*2][tx*5+j] = v.x; fin[ty*2+1][tx*5+j] = v.y;
    }
    __syncthreads();
    if (tid < 64) {
        int q = q0 + tid;
        float* cat = g_cat + (size_t)q * 2112;
        #pragma unroll
        for (int c = 0; c < 16; c++) cat[h*16+c] = fin[tid][c];
        const float* R = rot + q * 9; const float* T = trans + q * 3;
        float R0=R[0],R1=R[1],R2=R[2],R3=R[3],R4=R[4],R5=R[5],R6=R[6],R7=R[7],R8=R[8];
        float T0=T[0],T1=T[1],T2=T[2];
        #pragma unroll
        for (int p = 0; p < 8; p++) {
            float dx = fin[tid][16+p*3]-T0, dy = fin[tid][16+p*3+1]-T1, dz = fin[tid][16+p*3+2]-T2;
            float lx = R0*dx + R3*dy + R6*dz;
            float ly = R1*dx + R4*dy + R7*dz;
            float lz = R2*dx + R5*dy + R8*dz;
            int b = h*8+p;
            cat[192+b] = lx; cat[288+b] = ly; cat[384+b] = lz;
            cat[480+b] = sqrtf(lx*lx + ly*ly + lz*lz + 1e-8f);
        }
    }
}

// ---------------- o_pair (FFMA2 over h-pairs) ----------------
__global__ __launch_bounds__(256) void k5_opair(const float* __restrict__ z) {
    const int q = blockIdx.x, tid = threadIdx.x;
    const int part = tid >> 6, cq = tid & 63;
    __shared__ __align__(16) float aS[384 * 12];
    __shared__ float redS[3][12][128];
    u64 accx[6] = {}, accy[6] = {};
    for (int half = 0; half < 2; half++) {
        int kb = half * 384;
        __syncthreads();
        for (int lin = tid; lin < 384 * 12; lin += 256) {
            int hh = lin / 384, kk = lin - hh * 384;
            aS[kk * 12 + hh] = g_attn[((size_t)hh * NR + q) * NR + kb + kk];
        }
        __syncthreads();
        int klo = part * 96;
        #pragma unroll 2
        for (int kk = klo; kk < klo + 96; kk++) {
            float2 zv = *(const float2*)(z + ((size_t)q * NR + kb + kk) * 128 + 2 * cq);
            const u64* ap = (const u64*)(aS + kk * 12);
            u64 zx = bc2(zv.x), zy = bc2(zv.y);
            #pragma unroll
            for (int hp = 0; hp < 6; hp++) { fma2(accx[hp], ap[hp], zx); fma2(accy[hp], ap[hp], zy); }
        }
    }
    if (part > 0) {
        #pragma unroll
        for (int hp = 0; hp < 6; hp++) {
            float2 vx = up2(accx[hp]), vy = up2(accy[hp]);
            redS[part-1][2*hp][2*cq]     = vx.x;
            redS[part-1][2*hp][2*cq+1]   = vy.x;
            redS[part-1][2*hp+1][2*cq]   = vx.y;
            redS[part-1][2*hp+1][2*cq+1] = vy.y;
        }
    }
    __syncthreads();
    if (part == 0) {
        #pragma unroll
        for (int hp = 0; hp < 6; hp++) {
            float2 vx = up2(accx[hp]), vy = up2(accy[hp]);
            float o0x = vx.x, o0y = vy.x, o1x = vx.y, o1y = vy.y;
            #pragma unroll
            for (int r = 0; r < 3; r++) {
                o0x += redS[r][2*hp][2*cq];   o0y += redS[r][2*hp][2*cq+1];
                o1x += redS[r][2*hp+1][2*cq]; o1y += redS[r][2*hp+1][2*cq+1];
            }
            float2 w0 = make_float2(o0x, o0y), w1 = make_float2(o1x, o1y);
            *(float2*)(g_cat + (size_t)q * 2112 + 576 + (2*hp)   * 128 + 2*cq) = w0;
            *(float2*)(g_cat + (size_t)q * 2112 + 576 + (2*hp+1) * 128 + 2*cq) = w1;
        }
    }
}

extern "C" void kernel_launch(void* const* d_in, const int* in_sizes, int n_in,
                              void* d_out, int out_size) {
    const float* s     = (const float*)d_in[0];
    const float* z     = (const float*)d_in[1];
    const float* rot   = (const float*)d_in[2];
    const float* trans = (const float*)d_in[3];
    const float* mask  = (const float*)d_in[4];
    const float* Wq    = (const float*)d_in[5];
    const float* bq    = (const float*)d_in[6];
    const float* Wqp   = (const float*)d_in[7];
    const float* bqp   = (const float*)d_in[8];
    const float* Wkv   = (const float*)d_in[9];
    const float* bkv   = (const float*)d_in[10];
    const float* Wkvp  = (const float*)d_in[11];
    const float* bkvp  = (const float*)d_in[12];
    const float* Wb    = (const float*)d_in[13];
    const float* bbv   = (const float*)d_in[14];
    const float* hw    = (const float*)d_in[15];
    const float* Wout  = (const float*)d_in[16];
    const float* bout  = (const float*)d_in[17];
    float* out = (float*)d_out;

    gemm2<<<dim3(3, 12), 256>>>(s, Wq,   bq,   192, 384, 0, 0);
    gemm2<<<dim3(6, 12), 256>>>(s, Wkv,  bkv,  384, 384, 0, 192);
    gemm2<<<dim3(3, 12), 256>>>(s, Wqp,  bqp,  144, 384, 0, 576);
    gemm2<<<dim3(7, 12), 256>>>(s, Wkvp, bkvp, 432, 384, 0, 720);
    k1b_points<<<NR, 192>>>(rot, trans);
    k2_bbias<<<NR * 3, 128>>>(z, Wb, bbv);
    k3_attn<<<dim3(96, 12), 256>>>(hw, mask);
    k4_out<<<dim3(12, 12), 256>>>(rot, trans);
    k5_opair<<<NR, 256>>>(z);
    gemm2<<<dim3(6, 12, 2), 256>>>(nullptr, Wout, nullptr, 384, 2112, 2, 0);
    kcomb<<<1152, 256>>>(bout, out);
}